// round 4
// baseline (speedup 1.0000x reference)
#include <cuda_runtime.h>

namespace {
constexpr int T_STEPS = 64;
constexpr int S_DIM = 16;
constexpr int B_DIM = 2048;
constexpr int SB = S_DIM * B_DIM;  // 32768 rows
constexpr int R = 64;              // rows per block
constexpr int NT = 128;
constexpr int PAD = 68;            // floats per transposed column
constexpr int ZSTR = 64 * PAD;     // one z buffer
constexpr int SMEM_FLOATS = 4096 + 2 * ZSTR + 4;
constexpr int SMEM_BYTES = SMEM_FLOATS * 4;
}

__device__ float g_cdT[64 * B_DIM];  // (context @ Wc)^T : [Z][B]

__global__ void ctx_kernel(const float* __restrict__ context,
                           const float* __restrict__ Wc) {
    int idx = blockIdx.x * blockDim.x + threadIdx.x;  // over Z*B
    int z = idx >> 11, b = idx & (B_DIM - 1);
    float acc = 0.f;
#pragma unroll
    for (int c = 0; c < 64; ++c)
        acc = fmaf(context[b * 64 + c], Wc[c * 64 + z], acc);
    g_cdT[idx] = acc;
}

__device__ __forceinline__ unsigned long long pack2(float x, float y) {
    unsigned long long r;
    asm("mov.b64 %0, {%1, %2};" : "=l"(r) : "f"(x), "f"(y));
    return r;
}
__device__ __forceinline__ void unpack2(unsigned long long v, float& x, float& y) {
    asm("mov.b64 {%0, %1}, %2;" : "=f"(x), "=f"(y) : "l"(v));
}
__device__ __forceinline__ void ffma2(unsigned long long& d, unsigned long long a,
                                      unsigned long long b) {
    asm("fma.rn.f32x2 %0, %1, %2, %0;" : "+l"(d) : "l"(a), "l"(b));
}

// 64x64x64 tile GEMM: acc[i][q] accumulates rows rg+i, col pair (cg+2q, cg+2q+1)
__device__ __forceinline__ void gemm64(const float* __restrict__ zrb,
                                       const float* __restrict__ Wsh, int rg, int cg,
                                       unsigned long long acc[4][4]) {
#pragma unroll 8
    for (int k = 0; k < 64; ++k) {
        float4 z4 = *(const float4*)(zrb + k * PAD + rg);
        ulonglong2 wa = *(const ulonglong2*)(Wsh + k * 64 + cg);
        ulonglong2 wb = *(const ulonglong2*)(Wsh + k * 64 + cg + 4);
        unsigned long long zr0 = pack2(z4.x, z4.x), zr1 = pack2(z4.y, z4.y);
        unsigned long long zr2 = pack2(z4.z, z4.z), zr3 = pack2(z4.w, z4.w);
        ffma2(acc[0][0], zr0, wa.x); ffma2(acc[0][1], zr0, wa.y);
        ffma2(acc[0][2], zr0, wb.x); ffma2(acc[0][3], zr0, wb.y);
        ffma2(acc[1][0], zr1, wa.x); ffma2(acc[1][1], zr1, wa.y);
        ffma2(acc[1][2], zr1, wb.x); ffma2(acc[1][3], zr1, wb.y);
        ffma2(acc[2][0], zr2, wa.x); ffma2(acc[2][1], zr2, wa.y);
        ffma2(acc[2][2], zr2, wb.x); ffma2(acc[2][3], zr2, wb.y);
        ffma2(acc[3][0], zr3, wa.x); ffma2(acc[3][1], zr3, wa.y);
        ffma2(acc[3][2], zr3, wb.x); ffma2(acc[3][3], zr3, wb.y);
    }
}

__global__ void __launch_bounds__(NT, 4) scan_kernel(
    const float* __restrict__ z0, const float* __restrict__ eps,
    const float* __restrict__ W, const float* __restrict__ bvec,
    const float* __restrict__ sigmas, float* __restrict__ out) {
    extern __shared__ float smem[];
    float* Wsh = smem;                 // [64][64]
    float* zsh = smem + 4096;          // 2 buffers, [c][r] padded
    float* red = smem + 4096 + 2 * ZSTR;

    const int tid = threadIdx.x;
    const int r0 = blockIdx.x * R;
    const float dt = 1.0f / T_STEPS;

    {   // load W (coalesced float4)
        const float4* Wg = (const float4*)W;
        float4* Ws4 = (float4*)Wsh;
#pragma unroll
        for (int k = 0; k < 8; ++k) Ws4[tid + k * NT] = Wg[tid + k * NT];
    }

    // unified tile mapping: rows rg..rg+3, cols cg..cg+7
    const int rg = (tid & 15) * 4;
    const int cg = (tid >> 4) * 8;
    const int b0 = r0 & (B_DIM - 1);

    float* zs_out = out + 1;  // NOTE: only 4-byte aligned — scalar stores ONLY
    float acc_lw = 0.f;       // e^2 + z0^2 - u^2 - zT^2

    // ctx drift for my tile (constant across steps): cdv[c] lanes = rows
    float4 cdv[8];
#pragma unroll
    for (int c = 0; c < 8; ++c)
        cdv[c] = *(const float4*)(g_cdT + (cg + c) * B_DIM + b0 + rg);

    // init: z0 tile -> zs_out (scalar), +z0^2, scatter transposed into buf 0
#pragma unroll
    for (int i = 0; i < 4; ++i) {
        size_t gb = (size_t)(r0 + rg + i) * 64 + cg;
        float4 a = *(const float4*)(z0 + gb);
        float4 b4 = *(const float4*)(z0 + gb + 4);
        const float* av = (const float*)&a;
        const float* bv = (const float*)&b4;
#pragma unroll
        for (int c = 0; c < 4; ++c) {
            zs_out[gb + c] = av[c];
            zs_out[gb + 4 + c] = bv[c];
            acc_lw += av[c] * av[c];
            acc_lw += bv[c] * bv[c];
            zsh[(cg + c) * PAD + rg + i] = av[c];
            zsh[(cg + 4 + c) * PAD + rg + i] = bv[c];
        }
    }
    __syncthreads();

    float up[4][8];  // u_partial (with b*dt/std folded in), persistent
#pragma unroll
    for (int i = 0; i < 4; ++i)
#pragma unroll
        for (int c = 0; c < 8; ++c) up[i][c] = 0.f;
    float dtinv_prev = 0.f;  // 0 => first completion contributes u = up = 0
    int buf = 0;

#pragma unroll 1
    for (int t = 0; t < T_STEPS; ++t) {
        const float* zrb = zsh + buf * ZSTR;
        float* zwb = zsh + (buf ^ 1) * ZSTR;

        unsigned long long acc[4][4] = {};
        gemm64(zrb, Wsh, rg, cg, acc);  // drift = z_t @ W

        const float sig = __ldg(sigmas + t);
        const float stdv = sig * 0.125f;
        const float inv_std = 1.0f / stdv;
        const float dtinv = dt * inv_std;
        const float* eps_t = eps + (size_t)t * SB * 64;
        float* zo = zs_out + (size_t)(t + 1) * SB * 64;
        const bool last = (t == T_STEPS - 1);

#pragma unroll
        for (int h = 0; h < 2; ++h) {
            const int cb = cg + 4 * h;
            float4 e4[4];
#pragma unroll
            for (int i = 0; i < 4; ++i)
                e4[i] = __ldcs((const float4*)(eps_t +
                        (size_t)(r0 + rg + i) * 64 + cb));
#pragma unroll
            for (int q2 = 0; q2 < 2; ++q2) {
                const int q = 2 * h + q2;
                const int c0 = 4 * h + 2 * q2;  // local col of pair
                const float bt0 = __ldg(bvec + t * 64 + cg + c0);
                const float bt1 = __ldg(bvec + t * 64 + cg + c0 + 1);
                const float bt0d = bt0 * dtinv, bt1d = bt1 * dtinv;
                float4 zp0 = *(const float4*)(zrb + (cg + c0) * PAD + rg);
                float4 zp1 = *(const float4*)(zrb + (cg + c0 + 1) * PAD + rg);
                float4 zn0, zn1;
#pragma unroll
                for (int i = 0; i < 4; ++i) {
                    float d0, d1;
                    unpack2(acc[i][q], d0, d1);
                    // complete u for previous step (dtinv_prev=0 at t=0)
                    float u0 = fmaf(d0, dtinv_prev, up[i][c0]);
                    float u1 = fmaf(d1, dtinv_prev, up[i][c0 + 1]);
                    acc_lw -= u0 * u0;
                    acc_lw -= u1 * u1;
                    float e0 = ((const float*)&e4[i])[2 * q2];
                    float e1 = ((const float*)&e4[i])[2 * q2 + 1];
                    float zpv0 = ((const float*)&zp0)[i];
                    float zpv1 = ((const float*)&zp1)[i];
                    float mu0 = d0 + ((const float*)&cdv[c0])[i] + bt0;
                    float mu1 = d1 + ((const float*)&cdv[c0 + 1])[i] + bt1;
                    float z_0 = fmaf(stdv, e0, fmaf(mu0, dt, zpv0));
                    float z_1 = fmaf(stdv, e1, fmaf(mu1, dt, zpv1));
                    up[i][c0]     = fmaf(zpv0 - z_0, inv_std, bt0d);
                    up[i][c0 + 1] = fmaf(zpv1 - z_1, inv_std, bt1d);
                    acc_lw += e0 * e0;
                    acc_lw += e1 * e1;
                    if (last) { acc_lw -= z_0 * z_0; acc_lw -= z_1 * z_1; }
                    ((float*)&zn0)[i] = z_0;
                    ((float*)&zn1)[i] = z_1;
                    size_t go = (size_t)(r0 + rg + i) * 64 + cg + c0;
                    __stcs(zo + go, z_0);       // scalar: zs_out base is
                    __stcs(zo + go + 1, z_1);   // only 4-byte aligned
                }
                *(float4*)(zwb + (cg + c0) * PAD + rg) = zn0;
                *(float4*)(zwb + (cg + c0 + 1) * PAD + rg) = zn1;
            }
        }
        dtinv_prev = dtinv;
        buf ^= 1;
        __syncthreads();
    }

    // final drift = z_T @ W to complete u at t = T-1
    {
        const float* zrb = zsh + buf * ZSTR;
        unsigned long long acc[4][4] = {};
        gemm64(zrb, Wsh, rg, cg, acc);
#pragma unroll
        for (int q = 0; q < 4; ++q)
#pragma unroll
            for (int i = 0; i < 4; ++i) {
                float d0, d1;
                unpack2(acc[i][q], d0, d1);
                float u0 = fmaf(d0, dtinv_prev, up[i][2 * q]);
                float u1 = fmaf(d1, dtinv_prev, up[i][2 * q + 1]);
                acc_lw -= u0 * u0;
                acc_lw -= u1 * u1;
            }
    }

    // block-reduce acc_lw, out[0] += 0.5/S * sum
#pragma unroll
    for (int off = 16; off; off >>= 1)
        acc_lw += __shfl_down_sync(0xffffffffu, acc_lw, off);
    if ((tid & 31) == 0) red[tid >> 5] = acc_lw;
    __syncthreads();
    if (tid == 0) {
        float s = red[0] + red[1] + red[2] + red[3];
        atomicAdd(out, (0.5f / S_DIM) * s);
    }
}

extern "C" void kernel_launch(void* const* d_in, const int* in_sizes, int n_in,
                              void* d_out, int out_size) {
    (void)in_sizes; (void)n_in; (void)out_size;
    const float* z0      = (const float*)d_in[0];
    const float* eps     = (const float*)d_in[1];
    const float* context = (const float*)d_in[2];
    const float* W       = (const float*)d_in[3];
    const float* Wc      = (const float*)d_in[4];
    const float* bvec    = (const float*)d_in[5];
    const float* sigmas  = (const float*)d_in[6];
    float* out = (float*)d_out;

    cudaFuncSetAttribute(scan_kernel,
                         cudaFuncAttributeMaxDynamicSharedMemorySize, SMEM_BYTES);
    cudaMemsetAsync(out, 0, sizeof(float));
    ctx_kernel<<<(64 * B_DIM) / 256, 256>>>(context, Wc);  // g_cdT = (ctx @ Wc)^T
    scan_kernel<<<SB / R, NT, SMEM_BYTES>>>(z0, eps, W, bvec, sigmas, out);
}

// round 5
// speedup vs baseline: 2.1192x; 2.1192x over previous
#include <cuda_runtime.h>
#include <cstdint>

namespace {
constexpr int T_STEPS = 64;
constexpr int S_DIM = 16;
constexpr int B_DIM = 2048;
constexpr int SB = S_DIM * B_DIM;  // 32768 rows
constexpr int R = 64;              // rows per block
constexpr int NT = 128;
constexpr int PAD = 68;
// smem: Wp[64*64] + zT[64*68] + eps_sh[64*64]
constexpr int SMEM_FLOATS = 4096 + 64 * PAD + 4096;
constexpr int SMEM_BYTES = SMEM_FLOATS * 4;
}

__device__ float g_cd[B_DIM * 64];  // context @ Wc, row-major [B][Z]

__global__ void ctx_kernel(const float* __restrict__ context,
                           const float* __restrict__ Wc) {
    int idx = blockIdx.x * blockDim.x + threadIdx.x;  // over B*Z
    int b = idx >> 6, z = idx & 63;
    float acc = 0.f;
#pragma unroll
    for (int c = 0; c < 64; ++c)
        acc = fmaf(context[b * 64 + c], Wc[c * 64 + z], acc);
    g_cd[idx] = acc;
}

using u64 = unsigned long long;
__device__ __forceinline__ u64 pack2(float x, float y) {
    u64 r; asm("mov.b64 %0, {%1, %2};" : "=l"(r) : "f"(x), "f"(y)); return r;
}
__device__ __forceinline__ void unpack2(u64 v, float& x, float& y) {
    asm("mov.b64 {%0, %1}, %2;" : "=f"(x), "=f"(y) : "l"(v));
}
__device__ __forceinline__ void ffma2(u64& d, u64 a, u64 b) {
    asm("fma.rn.f32x2 %0, %1, %2, %0;" : "+l"(d) : "l"(a), "l"(b));
}
__device__ __forceinline__ u64 ffma2n(u64 a, u64 b, u64 c) {
    u64 d; asm("fma.rn.f32x2 %0, %1, %2, %3;" : "=l"(d) : "l"(a), "l"(b), "l"(c));
    return d;
}
__device__ __forceinline__ u64 add2(u64 a, u64 b) {
    u64 d; asm("add.rn.f32x2 %0, %1, %2;" : "=l"(d) : "l"(a), "l"(b)); return d;
}
__device__ __forceinline__ u64 mul2(u64 a, u64 b) {
    u64 d; asm("mul.rn.f32x2 %0, %1, %2;" : "=l"(d) : "l"(a), "l"(b)); return d;
}
__device__ __forceinline__ void cp16(uint32_t dst, const void* src) {
    asm volatile("cp.async.cg.shared.global [%0], [%1], 16;" :: "r"(dst), "l"(src));
}

__global__ void __launch_bounds__(NT, 4) scan_kernel(
    const float* __restrict__ z0, const float* __restrict__ eps,
    const float* __restrict__ W, const float* __restrict__ bvec,
    const float* __restrict__ sigmas, float* __restrict__ out) {
    extern __shared__ float smem[];
    float* Wp = smem;                  // [64][64] col-interleaved: Wp[k][2c+h]=W[k][c+32h]
    float* zT = smem + 4096;           // [c][r], stride PAD
    float* eps_sh = zT + 64 * PAD;     // [r][c] linear 64x64

    const int tid = threadIdx.x;
    const int l = tid & 31;
    const int rw = (tid >> 5) * 16;    // warp's base row
    const int r0 = blockIdx.x * R;
    const int b0 = r0 & (B_DIM - 1);
    const float dt = 1.0f / T_STEPS;
    const u64 dt2 = pack2(dt, dt);

    const uint32_t eps_sh_u32 = (uint32_t)__cvta_generic_to_shared(eps_sh);

    // fill Wp (col-interleaved for lane-pair u64 loads)
#pragma unroll
    for (int it = 0; it < 4096 / NT; ++it) {
        int idx = tid + it * NT;
        int k = idx >> 6, j = idx & 63;
        Wp[idx] = W[k * 64 + (j >> 1) + ((j & 1) << 5)];
    }

    float* zs_out = out + 1;  // 4B-aligned only: scalar global stores
    u64 z2[16], up2[16];
    u64 esq2 = 0, usq2 = 0;   // accumulate e^2+z0^2 and u^2+zT^2

    // init: load z0, emit z_samples[0], +z0^2, fill zT
#pragma unroll
    for (int g = 0; g < 4; ++g) {
        float4 v0, v1;
#pragma unroll
        for (int i = 0; i < 4; ++i) {
            int ri = 4 * g + i;
            size_t gb = (size_t)(r0 + rw + ri) * 64 + l;
            float a = z0[gb], b = z0[gb + 32];
            zs_out[gb] = a; zs_out[gb + 32] = b;
            u64 zz = pack2(a, b);
            z2[ri] = zz;
            up2[ri] = 0;
            ffma2(esq2, zz, zz);
            ((float*)&v0)[i] = a; ((float*)&v1)[i] = b;
        }
        *(float4*)(zT + l * PAD + rw + 4 * g) = v0;
        *(float4*)(zT + (l + 32) * PAD + rw + 4 * g) = v1;
    }
    __syncthreads();

    u64 dtinvp2 = 0;  // dt/std of previous step (0 => first completion is no-op)

#pragma unroll 1
    for (int t = 0;; ++t) {
        // prefetch eps(t) into smem (contiguous 16KB tile)
        if (t < T_STEPS) {
            const char* src = (const char*)(eps + ((size_t)t * SB + r0) * 64);
#pragma unroll
            for (int it = 0; it < 8; ++it) {
                int off = (tid + it * NT) * 16;
                cp16(eps_sh_u32 + off, src + off);
            }
            asm volatile("cp.async.commit_group;");
        }

        // GEMM: drift(z_t) ; acc[rp][h] = (drift[2rp][c_h], drift[2rp+1][c_h])
        u64 acc[8][2] = {};
#pragma unroll
        for (int k = 0; k < 64; ++k) {
            u64 w = *(const u64*)(Wp + k * 64 + 2 * l);
            float w0, w1; unpack2(w, w0, w1);
            u64 wd0 = pack2(w0, w0), wd1 = pack2(w1, w1);
#pragma unroll
            for (int g = 0; g < 4; ++g) {
                float4 z4 = *(const float4*)(zT + k * PAD + rw + 4 * g);
                u64 zp01 = ((const u64*)&z4)[0];
                u64 zp23 = ((const u64*)&z4)[1];
                ffma2(acc[2 * g][0], zp01, wd0);
                ffma2(acc[2 * g][1], zp01, wd1);
                ffma2(acc[2 * g + 1][0], zp23, wd0);
                ffma2(acc[2 * g + 1][1], zp23, wd1);
            }
        }

        if (t == T_STEPS) {
            // completion-only for u(T-1)
#pragma unroll
            for (int rp = 0; rp < 8; ++rp) {
                float a0, a1, b0f, b1f;
                unpack2(acc[rp][0], a0, a1);
                unpack2(acc[rp][1], b0f, b1f);
                u64 u2a = ffma2n(pack2(a0, b0f), dtinvp2, up2[2 * rp]);
                u64 u2b = ffma2n(pack2(a1, b1f), dtinvp2, up2[2 * rp + 1]);
                ffma2(usq2, u2a, u2a);
                ffma2(usq2, u2b, u2b);
            }
            break;
        }

        // per-step uniforms
        const float sig = __ldg(sigmas + t);
        const float stdv = sig * 0.125f;
        const float inv_std = 1.0f / stdv;
        const float dtinv = dt * inv_std;
        const u64 std2 = pack2(stdv, stdv);
        const u64 dtinv2 = pack2(dtinv, dtinv);
        const u64 ndtinv2 = pack2(-dtinv, -dtinv);
        const u64 bt2 = pack2(__ldg(bvec + t * 64 + l), __ldg(bvec + t * 64 + l + 32));
        const u64 btd2 = mul2(bt2, dtinv2);
        float* zo = zs_out + (size_t)(t + 1) * SB * 64;
        const bool last = (t == T_STEPS - 1);

        asm volatile("cp.async.wait_group 0;" ::: "memory");
        __syncthreads();  // all GEMM reads done; eps_sh(t) visible

#pragma unroll
        for (int g = 0; g < 4; ++g) {
            u64 znrow[4];
#pragma unroll
            for (int p = 0; p < 2; ++p) {
                const int rp = 2 * g + p;
                float a0, a1, c0f, c1f;
                unpack2(acc[rp][0], a0, a1);
                unpack2(acc[rp][1], c0f, c1f);
                u64 d2r[2] = {pack2(a0, c0f), pack2(a1, c1f)};
#pragma unroll
                for (int ii = 0; ii < 2; ++ii) {
                    const int ri = 2 * rp + ii;       // warp-local row 0..15
                    const int rb = rw + ri;           // block-local row
                    u64 d2 = d2r[ii];
                    // complete u(t-1)
                    u64 u2 = ffma2n(d2, dtinvp2, up2[ri]);
                    ffma2(usq2, u2, u2);
                    // forward update
                    u64 cd2 = pack2(__ldg(g_cd + (size_t)(b0 + rb) * 64 + l),
                                    __ldg(g_cd + (size_t)(b0 + rb) * 64 + l + 32));
                    u64 e2 = pack2(eps_sh[rb * 64 + l], eps_sh[rb * 64 + l + 32]);
                    u64 mu2 = add2(d2, add2(cd2, bt2));
                    u64 zn2 = ffma2n(e2, std2, ffma2n(mu2, dt2, z2[ri]));
                    u64 ne2 = e2 ^ 0x8000000080000000ull;
                    up2[ri] = ffma2n(mu2, ndtinv2, add2(ne2, btd2));
                    ffma2(esq2, e2, e2);
                    if (last) ffma2(usq2, zn2, zn2);
                    z2[ri] = zn2;
                    znrow[2 * p + ii] = zn2;
                    float s0, s1; unpack2(zn2, s0, s1);
                    size_t go = (size_t)(r0 + rb) * 64 + l;
                    __stcs(zo + go, s0);
                    __stcs(zo + go + 32, s1);
                }
            }
            // write zn to zT for next GEMM (float4 over rows, per col)
            float x0, x1, y0, y1, w0, w1, v0f, v1f;
            unpack2(znrow[0], x0, x1); unpack2(znrow[1], y0, y1);
            unpack2(znrow[2], w0, w1); unpack2(znrow[3], v0f, v1f);
            float4 s0 = {x0, y0, w0, v0f};
            float4 s1 = {x1, y1, w1, v1f};
            *(float4*)(zT + l * PAD + rw + 4 * g) = s0;
            *(float4*)(zT + (l + 32) * PAD + rw + 4 * g) = s1;
        }
        dtinvp2 = dtinv2;
        __syncthreads();  // zT(t+1) visible before next GEMM
    }

    // reduce lw = (0.5/S) * (esq - usq)
    float e0, e1, q0, q1;
    unpack2(esq2, e0, e1);
    unpack2(usq2, q0, q1);
    float lw = (e0 + e1) - (q0 + q1);
#pragma unroll
    for (int off = 16; off; off >>= 1)
        lw += __shfl_down_sync(0xffffffffu, lw, off);
    __syncthreads();           // eps_sh no longer needed; reuse for reduction
    if ((tid & 31) == 0) eps_sh[tid >> 5] = lw;
    __syncthreads();
    if (tid == 0) {
        float s = eps_sh[0] + eps_sh[1] + eps_sh[2] + eps_sh[3];
        atomicAdd(out, (0.5f / S_DIM) * s);
    }
}

extern "C" void kernel_launch(void* const* d_in, const int* in_sizes, int n_in,
                              void* d_out, int out_size) {
    (void)in_sizes; (void)n_in; (void)out_size;
    const float* z0      = (const float*)d_in[0];
    const float* eps     = (const float*)d_in[1];
    const float* context = (const float*)d_in[2];
    const float* W       = (const float*)d_in[3];
    const float* Wc      = (const float*)d_in[4];
    const float* bvec    = (const float*)d_in[5];
    const float* sigmas  = (const float*)d_in[6];
    float* out = (float*)d_out;

    cudaFuncSetAttribute(scan_kernel,
                         cudaFuncAttributeMaxDynamicSharedMemorySize, SMEM_BYTES);
    cudaMemsetAsync(out, 0, sizeof(float));
    ctx_kernel<<<(B_DIM * 64) / 256, 256>>>(context, Wc);
    scan_kernel<<<SB / R, NT, SMEM_BYTES>>>(z0, eps, W, bvec, sigmas, out);
}